// round 15
// baseline (speedup 1.0000x reference)
#include <cuda_runtime.h>
#include <cuda_fp16.h>
#include <cstdint>
#include <math.h>

#define NB 16
#define CI 512
#define CO 512
#define SD 512

// ---------------------------------------------------------------------------
__device__ float g_s[NB * CI];
__device__ float g_W2[CO * CI];
__device__ __half g_x[(size_t)NB * 32 * 32 * CI];   // [b][y][x][i] fp16, modulated
__device__ __half g_k[(size_t)9 * CO * CI];         // [tap][o][i] fp16
__device__ __half g_z[(size_t)NB * CO * 9 * 1024];  // [b][o][tap][32x32] fp16

// ---------------------------------------------------------------------------
__device__ __forceinline__ unsigned h2u(__half2 h) {
    return *reinterpret_cast<unsigned*>(&h);
}
__device__ __forceinline__ uint32_t smem_u32(const void* p) {
    uint32_t a;
    asm("{ .reg .u64 t; cvta.to.shared.u64 t, %1; cvt.u32.u64 %0, t; }"
        : "=r"(a) : "l"(p));
    return a;
}
__device__ __forceinline__ void cp16(uint32_t dst, const void* src) {
    asm volatile("cp.async.cg.shared.global [%0], [%1], 16;"
                 :: "r"(dst), "l"(src) : "memory");
}
__device__ __forceinline__ void cp_commit() {
    asm volatile("cp.async.commit_group;" ::: "memory");
}
__device__ __forceinline__ void ldmx4(uint32_t* r, uint32_t addr) {
    asm volatile("ldmatrix.sync.aligned.m8n8.x4.shared.b16 {%0,%1,%2,%3}, [%4];"
                 : "=r"(r[0]), "=r"(r[1]), "=r"(r[2]), "=r"(r[3]) : "r"(addr));
}
// fp16-accumulate MMA: d = a*b + c  (all f16)
__device__ __forceinline__ void mma_h(uint32_t* d, const uint32_t* a,
                                      uint32_t b0, uint32_t b1,
                                      uint32_t c0, uint32_t c1) {
    asm volatile(
        "mma.sync.aligned.m16n8k16.row.col.f16.f16.f16.f16 "
        "{%0,%1}, {%2,%3,%4,%5}, {%6,%7}, {%8,%9};"
        : "=r"(d[0]), "=r"(d[1])
        : "r"(a[0]), "r"(a[1]), "r"(a[2]), "r"(a[3]),
          "r"(b0), "r"(b1), "r"(c0), "r"(c1));
}

// ---------------------------------------------------------------------------
__global__ void k_style(const float* __restrict__ style, const float* __restrict__ mw,
                        const float* __restrict__ mb) {
    int b = blockIdx.x, i = threadIdx.x;
    __shared__ float st[SD];
    st[i] = style[b * SD + i];
    __syncthreads();
    const float* row = mw + (size_t)i * SD;
    float acc = 0.f;
#pragma unroll 4
    for (int j = 0; j < SD; j += 4) {
        float4 m = *(const float4*)(row + j);
        acc += m.x * st[j] + m.y * st[j + 1] + m.z * st[j + 2] + m.w * st[j + 3];
    }
    g_s[b * CI + i] = acc * 0.04419417382415922f + mb[i];
}

// prep_w: wsplit (bid<256) | w2 (256..767)
__global__ void __launch_bounds__(512)
k_prep_w(const float* __restrict__ cw) {
    int bid = blockIdx.x, tid = threadIdx.x;
    if (bid < 256) {
        int idx = bid * 512 + tid;
        int o = idx >> 8, ipair = idx & 255;
        int i = ipair * 2;
        const float* p0 = cw + ((size_t)o * CI + i) * 9;
        const float* p1 = p0 + 9;
        unsigned* pk = (unsigned*)g_k;
#pragma unroll
        for (int k = 0; k < 9; ++k) {
            unsigned v = h2u(__floats2half2_rn(p0[k], p1[k]));
            pk[((size_t)k * CO + o) * (CI / 2) + ipair] = v;
        }
    } else {
        int idx = (bid - 256) * 512 + tid;
        const float* p = cw + (size_t)idx * 9;
        float a = 0.f;
#pragma unroll
        for (int k = 0; k < 9; ++k) a += p[k] * p[k];
        g_W2[idx] = a;
    }
}

// prep_x: g_x[b,y,q,i] = fp16(x[b,i,y,q] * s[b,i])
__global__ void __launch_bounds__(512)
k_prep_x(const float* __restrict__ x) {
    int xb = blockIdx.x, tid = threadIdx.x;
    int b = xb >> 4;
    int y = (xb & 15) * 2 + (tid >> 8);
    int ipair = tid & 255;
    int i = ipair * 2;
    const float* s0 = x + ((size_t)(b * CI + i) * 32 + y) * 32;
    const float* s1 = s0 + 1024;
    float sv0 = g_s[b * CI + i], sv1 = g_s[b * CI + i + 1];
    unsigned pk[32];
#pragma unroll
    for (int q4 = 0; q4 < 8; ++q4) {
        float4 f0 = *(const float4*)(s0 + q4 * 4);
        float4 f1 = *(const float4*)(s1 + q4 * 4);
        pk[q4 * 4 + 0] = h2u(__floats2half2_rn(f0.x * sv0, f1.x * sv1));
        pk[q4 * 4 + 1] = h2u(__floats2half2_rn(f0.y * sv0, f1.y * sv1));
        pk[q4 * 4 + 2] = h2u(__floats2half2_rn(f0.z * sv0, f1.z * sv1));
        pk[q4 * 4 + 3] = h2u(__floats2half2_rn(f0.w * sv0, f1.w * sv1));
    }
    unsigned* px = (unsigned*)g_x;
    size_t rowbase = (size_t)(b * 32 + y) * 32 * (CI / 2) + (size_t)ipair;
#pragma unroll
    for (int q = 0; q < 32; ++q)
        px[rowbase + (size_t)q * (CI / 2)] = pk[q];
}

// ---------------------------------------------------------------------------
// Persistent z GEMM v6: fp16-accumulate HMMA, per-stage fp32 promotion.
// 288 CTAs (72 row-tiles of M=64 x 4 b-groups). A resident 64KB,
// B 3-stage ring (3x16KB) => 112KB smem/CTA, occupancy 2.
#define A_BYTES 65536
#define B_STG 16384
#define SMEM_Z (A_BYTES + 3 * B_STG)

__global__ void __launch_bounds__(256, 2)
k_zgemm() {
    extern __shared__ __align__(1024) char smem[];
    const uint32_t sb = smem_u32(smem);
    const uint32_t bbase = sb + A_BYTES;

    const int tid = threadIdx.x;
    const int wid = tid >> 5, ln = tid & 31;
    const int rt = blockIdx.x % 72;
    const int bg = blockIdx.x / 72;     // 0..3
    const int tp = rt >> 3;
    const int o0 = (rt & 7) * 64;
    const int wm = wid & 1, wn = wid >> 1;
    const int g = ln >> 2, t4 = ln & 3;

    const char* gA = (const char*)g_k;
    const char* gB = (const char*)g_x;

    // --- load full A (64 x 512 fp16 = 64KB; 16 kchunks of 4KB) ---
    {
        int r = tid >> 2;                        // 0..63
        uint32_t c = (uint32_t)(tid & 3) << 4;
        const char* sA = gA + ((size_t)(tp * CO + o0 + r) * CI) * 2 + c;
        uint32_t dA = sb + (uint32_t)(r * 64) + (c ^ (uint32_t)((r & 6) << 3));
#pragma unroll
        for (int kc = 0; kc < 16; ++kc)
            cp16(dA + kc * 4096, sA + kc * 64);
        cp_commit();
    }

    // --- B stage setup: 4 chunks of 16B per thread per stage (16KB) ---
    int brow[4];
    uint32_t bco[4], bdst[4];
#pragma unroll
    for (int j = 0; j < 4; ++j) {
        int id = tid + 256 * j;
        brow[j] = id >> 2;
        bco[j] = (uint32_t)(id & 3) << 4;
        bdst[j] = bbase + (uint32_t)(brow[j] * 64) +
                  (bco[j] ^ (uint32_t)((brow[j] & 6) << 3));
    }

    // --- ldmatrix fragment addresses ---
    uint32_t aAddr[2], bAddr[4];
#pragma unroll
    for (int mt = 0; mt < 2; ++mt) {
        int mrow = wm * 32 + mt * 16 + (ln & 15);
        uint32_t hi = (uint32_t)(ln >> 4) << 4;
        aAddr[mt] = sb + (uint32_t)(mrow * 64) + (hi ^ (uint32_t)((mrow & 6) << 3));
    }
#pragma unroll
    for (int np = 0; np < 4; ++np) {
        int nrow = wn * 64 + np * 16 + ((ln >> 4) & 1) * 8 + (ln & 7);
        uint32_t hi = (uint32_t)((ln >> 3) & 1) << 4;
        bAddr[np] = bbase + (uint32_t)(nrow * 64) + (hi ^ (uint32_t)((nrow & 6) << 3));
    }

    float acc[2][8][4];
#pragma unroll
    for (int mt = 0; mt < 2; ++mt)
#pragma unroll
        for (int nt = 0; nt < 8; ++nt)
#pragma unroll
            for (int e = 0; e < 4; ++e) acc[mt][nt][e] = 0.f;

    // --- prologue: B stages 0,1 ---
#pragma unroll
    for (int s = 0; s < 2; ++s) {
        int nt1 = s >> 4, ks1 = s & 15;
        int b1 = bg * 4 + (nt1 >> 2), nb1 = nt1 & 3;
        uint32_t so = (uint32_t)(s % 3) * B_STG;
        size_t base = ((size_t)(b1 * 1024 + nb1 * 256) * CI + ks1 * 32) * 2;
#pragma unroll
        for (int j = 0; j < 4; ++j)
            cp16(bdst[j] + so, gB + base + (size_t)brow[j] * CI * 2 + bco[j]);
        cp_commit();
    }

    const uint32_t zz = 0;
    int slot = 0, slot2 = 2;
#pragma unroll 1
    for (int gs = 0; gs < 256; ++gs) {
        asm volatile("cp.async.wait_group 1;" ::: "memory");
        __syncthreads();

        if (gs + 2 < 256) {
            int g1 = gs + 2;
            int nt1 = g1 >> 4, ks1 = g1 & 15;
            int b1 = bg * 4 + (nt1 >> 2), nb1 = nt1 & 3;
            uint32_t so = (uint32_t)slot2 * B_STG;
            size_t base = ((size_t)(b1 * 1024 + nb1 * 256) * CI + ks1 * 32) * 2;
#pragma unroll
            for (int j = 0; j < 4; ++j)
                cp16(bdst[j] + so, gB + base + (size_t)brow[j] * CI * 2 + bco[j]);
        }
        cp_commit();

        const int ks = gs & 15;
        const uint32_t aOff = (uint32_t)(ks * 4096);
        const uint32_t bOff = (uint32_t)slot * B_STG;

#pragma unroll
        for (int mt = 0; mt < 2; ++mt) {
            uint32_t fa0[4], fa1[4];
            ldmx4(fa0, aAddr[mt] + aOff);
            ldmx4(fa1, (aAddr[mt] + aOff) ^ 32u);
#pragma unroll
            for (int np = 0; np < 4; ++np) {
                uint32_t fb0[4], fb1[4];
                ldmx4(fb0, bAddr[np] + bOff);
                ldmx4(fb1, (bAddr[np] + bOff) ^ 32u);
                uint32_t h0[2], h1[2];
                mma_h(h0, fa0, fb0[0], fb0[1], zz, zz);
                mma_h(h1, fa0, fb0[2], fb0[3], zz, zz);
                mma_h(h0, fa1, fb1[0], fb1[1], h0[0], h0[1]);
                mma_h(h1, fa1, fb1[2], fb1[3], h1[0], h1[1]);
                // promote stage-partial (fp16) into fp32 master
                float2 p;
                float* a0 = acc[mt][2 * np];
                float* a1 = acc[mt][2 * np + 1];
                p = __half22float2(*(__half2*)&h0[0]); a0[0] += p.x; a0[1] += p.y;
                p = __half22float2(*(__half2*)&h0[1]); a0[2] += p.x; a0[3] += p.y;
                p = __half22float2(*(__half2*)&h1[0]); a1[0] += p.x; a1[1] += p.y;
                p = __half22float2(*(__half2*)&h1[1]); a1[2] += p.x; a1[3] += p.y;
            }
        }

        slot = (slot == 2) ? 0 : slot + 1;
        slot2 = (slot2 == 2) ? 0 : slot2 + 1;

        if (ks == 15) {
            int nt = gs >> 4;
            int b = bg * 4 + (nt >> 2), nblk = nt & 3;
#pragma unroll
            for (int mt = 0; mt < 2; ++mt)
#pragma unroll
                for (int rr = 0; rr < 2; ++rr) {
                    int o = o0 + wm * 32 + mt * 16 + rr * 8 + g;
                    __half2* zb = (__half2*)(g_z + ((size_t)(b * CO + o) * 9 + tp) * 1024);
#pragma unroll
                    for (int nt8 = 0; nt8 < 8; ++nt8) {
                        int nl = wn * 64 + nt8 * 8 + 2 * t4;
                        int sp = nblk * 256 + nl;
                        zb[sp >> 1] = __floats2half2_rn(acc[mt][nt8][rr * 2],
                                                        acc[mt][nt8][rr * 2 + 1]);
                    }
                }
#pragma unroll
            for (int mt = 0; mt < 2; ++mt)
#pragma unroll
                for (int nt8 = 0; nt8 < 8; ++nt8)
#pragma unroll
                    for (int e = 0; e < 4; ++e) acc[mt][nt8][e] = 0.f;
        }
    }
}

// ---------------------------------------------------------------------------
// Combine v3 (unchanged).
__global__ void __launch_bounds__(256)
k_comb(const float* __restrict__ noise, const float* __restrict__ nwp,
       const float* __restrict__ ab, float* __restrict__ out) {
    extern __shared__ float sm[];
    float* zs = sm;                 // 288*36 = 10368
    float* us = sm + 10368;         // 3*34*64 = 6528
    float* red = sm + 16896;        // 8

    const int bo = blockIdx.x;
    const int b = bo >> 9, o = bo & 511;
    const int tid = threadIdx.x;

    {
        float part = 0.f;
        const float* wrow = g_W2 + (size_t)o * CI;
        const float* srow = g_s + b * CI;
#pragma unroll
        for (int j = tid; j < CI; j += 256) {
            float sv = srow[j];
            part += sv * sv * wrow[j];
        }
#pragma unroll
        for (int off = 16; off; off >>= 1)
            part += __shfl_xor_sync(0xFFFFFFFFu, part, off);
        if ((tid & 31) == 0) red[tid >> 5] = part;
    }

    const __half2* zp2 = (const __half2*)(g_z + (size_t)bo * 9216);
#pragma unroll
    for (int j = tid; j < 4608; j += 256) {
        float2 f = __half22float2(zp2[j]);
        int e = 2 * j;
        int row = e >> 5;
        int q = e & 31;
        *(float2*)(zs + row * 36 + 2 + q) = f;
    }
#pragma unroll
    for (int j = tid; j < 576; j += 256) {
        int row = j >> 1;
        *(float2*)(zs + row * 36 + (j & 1) * 34) = make_float2(0.f, 0.f);
    }
#pragma unroll
    for (int j = tid; j < 192; j += 256) {
        int r = j >> 5;
        int xx = (j & 31) * 2;
        *(float2*)(us + ((r >> 1) * 34 + (r & 1) * 33) * 64 + xx) = make_float2(0.f, 0.f);
    }
    __syncthreads();

    float asum = red[0] + red[1] + red[2] + red[3] +
                 red[4] + red[5] + red[6] + red[7];
    const float alp = 0.014731391274719739f *
                      rsqrtf(asum * (1.0f / 4608.0f) + 1e-8f) * 0.0625f;

#pragma unroll 1
    for (int m = tid; m < 1536; m += 256) {
        int qq = m & 15, y = (m >> 4) & 31, ky = m >> 9;
        const float* r0 = zs + ((ky * 3 + 0) * 32 + y) * 36 + 2 * qq;
        const float* r1 = r0 + 32 * 36;
        const float* r2 = r1 + 32 * 36;
        float2 A0 = *(const float2*)r0, B0 = *(const float2*)(r0 + 2),
               C0 = *(const float2*)(r0 + 4);
        float2 A1 = *(const float2*)r1, B1 = *(const float2*)(r1 + 2),
               C1 = *(const float2*)(r1 + 4);
        float2 A2 = *(const float2*)r2, B2 = *(const float2*)(r2 + 2),
               C2 = *(const float2*)(r2 + 4);
        float p1 = A1.y, p2 = A2.y;
        float q0 = B0.x, q1 = B1.x, q2 = B2.x;
        float s0 = B0.y, s1 = B1.y, s2 = B2.y;
        float t0 = C0.x, t1 = C1.x;
        float4 u;
        u.x = p1 + 3.f * p2 + 3.f * q0 + 3.f * q1 + q2 + s0;
        u.y = p2 + q0 + 3.f * q1 + 3.f * q2 + 3.f * s0 + s1;
        u.z = q1 + 3.f * q2 + 3.f * s0 + 3.f * s1 + s2 + t0;
        u.w = q2 + s0 + 3.f * s1 + 3.f * s2 + 3.f * t0 + t1;
        *(float4*)(us + (ky * 34 + y + 1) * 64 + 4 * qq) = u;
    }
    __syncthreads();

    const float bia = ab[o];
    const float nw = *nwp;
    const float* nzb = noise + b * 4096;
    float* ob = out + (size_t)bo * 4096;
#pragma unroll 1
    for (int m = tid; m < 1024; m += 256) {
        int X2 = (m & 31) * 2, p = m >> 5;
        const float* v0 = us + (0 * 34 + p) * 64 + X2;
        const float* v1 = us + (1 * 34 + p) * 64 + X2;
        const float* v2 = us + (2 * 34 + p) * 64 + X2;
        float2 a01 = *(const float2*)(v0 + 64), a02 = *(const float2*)(v0 + 128);
        float2 a10 = *(const float2*)(v1),      a11 = *(const float2*)(v1 + 64);
        float2 a12 = *(const float2*)(v1 + 128);
        float2 a20 = *(const float2*)(v2),      a21 = *(const float2*)(v2 + 64);
        float2 o0v, o1v;
        o0v.x = a10.x + 3.f * a20.x + 3.f * a01.x + 3.f * a11.x + a21.x + a02.x;
        o0v.y = a10.y + 3.f * a20.y + 3.f * a01.y + 3.f * a11.y + a21.y + a02.y;
        o1v.x = a20.x + a01.x + 3.f * a11.x + 3.f * a21.x + 3.f * a02.x + a12.x;
        o1v.y = a20.y + a01.y + 3.f * a11.y + 3.f * a21.y + 3.f * a02.y + a12.y;
        int j0 = (2 * p) * 64 + X2;
        float2 n0 = *(const float2*)(nzb + j0);
        float2 n1 = *(const float2*)(nzb + j0 + 64);
        float2 w0, w1;
        w0.x = o0v.x * alp + nw * n0.x + bia;
        w0.y = o0v.y * alp + nw * n0.y + bia;
        w1.x = o1v.x * alp + nw * n1.x + bia;
        w1.y = o1v.y * alp + nw * n1.y + bia;
        w0.x = (w0.x > 0.f ? w0.x : 0.2f * w0.x) * 1.4142135623730951f;
        w0.y = (w0.y > 0.f ? w0.y : 0.2f * w0.y) * 1.4142135623730951f;
        w1.x = (w1.x > 0.f ? w1.x : 0.2f * w1.x) * 1.4142135623730951f;
        w1.y = (w1.y > 0.f ? w1.y : 0.2f * w1.y) * 1.4142135623730951f;
        *(float2*)(ob + j0) = w0;
        *(float2*)(ob + j0 + 64) = w1;
    }
}

// ---------------------------------------------------------------------------
extern "C" void kernel_launch(void* const* d_in, const int* in_sizes, int n_in,
                              void* d_out, int out_size) {
    const float* x           = (const float*)d_in[0];
    const float* style       = (const float*)d_in[1];
    const float* noise       = (const float*)d_in[2];
    const float* conv_weight = (const float*)d_in[3];
    const float* mod_weight  = (const float*)d_in[4];
    const float* mod_bias    = (const float*)d_in[5];
    const float* noise_w     = (const float*)d_in[6];
    const float* act_bias    = (const float*)d_in[7];
    float* out = (float*)d_out;

    cudaFuncSetAttribute(k_zgemm, cudaFuncAttributeMaxDynamicSharedMemorySize, SMEM_Z);
    cudaFuncSetAttribute(k_comb, cudaFuncAttributeMaxDynamicSharedMemorySize, 67648);

    // zgemm at launch index 3 -> lands in the ncu capture window.
    k_style<<<NB, 512>>>(style, mod_weight, mod_bias);
    k_prep_w<<<768, 512>>>(conv_weight);
    k_prep_x<<<256, 512>>>(x);
    k_zgemm<<<288, 256, SMEM_Z>>>();
    k_comb<<<NB * CO, 256, 67648>>>(noise, noise_w, act_bias, out);
}

// round 16
// speedup vs baseline: 1.0550x; 1.0550x over previous
#include <cuda_runtime.h>
#include <cuda_fp16.h>
#include <cstdint>
#include <math.h>

#define NB 16
#define CI 512
#define CO 512
#define SD 512

// ---------------------------------------------------------------------------
__device__ float g_s[NB * CI];
__device__ float g_W2[CO * CI];
__device__ __half g_x[(size_t)NB * 32 * 32 * CI];   // [b][y][x][i] fp16, modulated
__device__ __half g_k[(size_t)9 * CO * CI];         // [tap][o][i] fp16
__device__ __half g_z[(size_t)NB * CO * 9 * 1024];  // [b][o][tap][32x32] fp16

// ---------------------------------------------------------------------------
__device__ __forceinline__ unsigned h2u(__half2 h) {
    return *reinterpret_cast<unsigned*>(&h);
}
__device__ __forceinline__ uint32_t smem_u32(const void* p) {
    uint32_t a;
    asm("{ .reg .u64 t; cvta.to.shared.u64 t, %1; cvt.u32.u64 %0, t; }"
        : "=r"(a) : "l"(p));
    return a;
}
__device__ __forceinline__ void cp16(uint32_t dst, const void* src) {
    asm volatile("cp.async.cg.shared.global [%0], [%1], 16;"
                 :: "r"(dst), "l"(src) : "memory");
}
__device__ __forceinline__ void cp_commit() {
    asm volatile("cp.async.commit_group;" ::: "memory");
}
__device__ __forceinline__ void ldmx4(uint32_t* r, uint32_t addr) {
    asm volatile("ldmatrix.sync.aligned.m8n8.x4.shared.b16 {%0,%1,%2,%3}, [%4];"
                 : "=r"(r[0]), "=r"(r[1]), "=r"(r[2]), "=r"(r[3]) : "r"(addr));
}
__device__ __forceinline__ void mma_f16(float* d, const uint32_t* a,
                                        uint32_t b0, uint32_t b1) {
    asm volatile(
        "mma.sync.aligned.m16n8k16.row.col.f32.f16.f16.f32 "
        "{%0,%1,%2,%3}, {%4,%5,%6,%7}, {%8,%9}, {%0,%1,%2,%3};"
        : "+f"(d[0]), "+f"(d[1]), "+f"(d[2]), "+f"(d[3])
        : "r"(a[0]), "r"(a[1]), "r"(a[2]), "r"(a[3]), "r"(b0), "r"(b1));
}

// ---------------------------------------------------------------------------
__global__ void k_style(const float* __restrict__ style, const float* __restrict__ mw,
                        const float* __restrict__ mb) {
    int b = blockIdx.x, i = threadIdx.x;
    __shared__ float st[SD];
    st[i] = style[b * SD + i];
    __syncthreads();
    const float* row = mw + (size_t)i * SD;
    float acc = 0.f;
#pragma unroll 4
    for (int j = 0; j < SD; j += 4) {
        float4 m = *(const float4*)(row + j);
        acc += m.x * st[j] + m.y * st[j + 1] + m.z * st[j + 2] + m.w * st[j + 3];
    }
    g_s[b * CI + i] = acc * 0.04419417382415922f + mb[i];
}

// prep_w: wsplit (bid<256) | w2 (256..767)
__global__ void __launch_bounds__(512)
k_prep_w(const float* __restrict__ cw) {
    int bid = blockIdx.x, tid = threadIdx.x;
    if (bid < 256) {
        int idx = bid * 512 + tid;
        int o = idx >> 8, ipair = idx & 255;
        int i = ipair * 2;
        const float* p0 = cw + ((size_t)o * CI + i) * 9;
        const float* p1 = p0 + 9;
        unsigned* pk = (unsigned*)g_k;
#pragma unroll
        for (int k = 0; k < 9; ++k) {
            unsigned v = h2u(__floats2half2_rn(p0[k], p1[k]));
            pk[((size_t)k * CO + o) * (CI / 2) + ipair] = v;
        }
    } else {
        int idx = (bid - 256) * 512 + tid;
        const float* p = cw + (size_t)idx * 9;
        float a = 0.f;
#pragma unroll
        for (int k = 0; k < 9; ++k) a += p[k] * p[k];
        g_W2[idx] = a;
    }
}

// prep_x: g_x[b,y,q,i] = fp16(x[b,i,y,q] * s[b,i])
__global__ void __launch_bounds__(512)
k_prep_x(const float* __restrict__ x) {
    int xb = blockIdx.x, tid = threadIdx.x;
    int b = xb >> 4;
    int y = (xb & 15) * 2 + (tid >> 8);
    int ipair = tid & 255;
    int i = ipair * 2;
    const float* s0 = x + ((size_t)(b * CI + i) * 32 + y) * 32;
    const float* s1 = s0 + 1024;
    float sv0 = g_s[b * CI + i], sv1 = g_s[b * CI + i + 1];
    unsigned pk[32];
#pragma unroll
    for (int q4 = 0; q4 < 8; ++q4) {
        float4 f0 = *(const float4*)(s0 + q4 * 4);
        float4 f1 = *(const float4*)(s1 + q4 * 4);
        pk[q4 * 4 + 0] = h2u(__floats2half2_rn(f0.x * sv0, f1.x * sv1));
        pk[q4 * 4 + 1] = h2u(__floats2half2_rn(f0.y * sv0, f1.y * sv1));
        pk[q4 * 4 + 2] = h2u(__floats2half2_rn(f0.z * sv0, f1.z * sv1));
        pk[q4 * 4 + 3] = h2u(__floats2half2_rn(f0.w * sv0, f1.w * sv1));
    }
    unsigned* px = (unsigned*)g_x;
    size_t rowbase = (size_t)(b * 32 + y) * 32 * (CI / 2) + (size_t)ipair;
#pragma unroll
    for (int q = 0; q < 32; ++q)
        px[rowbase + (size_t)q * (CI / 2)] = pk[q];
}

// ---------------------------------------------------------------------------
// Persistent z GEMM v7: 4-stage windows over an 8-slot B ring, f32-acc HMMA.
// 144 CTAs (72 o-tiles of M=64 x 2 b-groups of 8 batches). A resident 64KB,
// B ring 8x16KB => 192KB/CTA, 1 CTA/SM, single wave. 512 stages, 128 windows.
#define A_BYTES 65536
#define B_STG 16384
#define SMEM_Z (A_BYTES + 8 * B_STG)

__global__ void __launch_bounds__(256, 1)
k_zgemm() {
    extern __shared__ __align__(1024) char smem[];
    const uint32_t sb = smem_u32(smem);
    const uint32_t bbase = sb + A_BYTES;

    const int tid = threadIdx.x;
    const int wid = tid >> 5, ln = tid & 31;
    const int rt = blockIdx.x % 72;
    const int bg = blockIdx.x / 72;     // 0..1, each owns 8 b's
    const int tp = rt >> 3;
    const int o0 = (rt & 7) * 64;
    const int wm = wid & 1, wn = wid >> 1;
    const int g = ln >> 2, t4 = ln & 3;

    const char* gA = (const char*)g_k;
    const char* gB = (const char*)g_x;

    // --- load full A (64 x 512 fp16 = 64KB; 16 kchunks of 4KB); own group ---
    {
        int r = tid >> 2;                        // 0..63
        uint32_t c = (uint32_t)(tid & 3) << 4;
        const char* sA = gA + ((size_t)(tp * CO + o0 + r) * CI) * 2 + c;
        uint32_t dA = sb + (uint32_t)(r * 64) + (c ^ (uint32_t)((r & 6) << 3));
#pragma unroll
        for (int kc = 0; kc < 16; ++kc)
            cp16(dA + kc * 4096, sA + kc * 64);
        cp_commit();
    }

    // --- B stage setup: 4 chunks of 16B per thread per stage (16KB) ---
    int brow[4];
    uint32_t bco[4], bdst[4];
#pragma unroll
    for (int j = 0; j < 4; ++j) {
        int id = tid + 256 * j;
        brow[j] = id >> 2;
        bco[j] = (uint32_t)(id & 3) << 4;
        bdst[j] = bbase + (uint32_t)(brow[j] * 64) +
                  (bco[j] ^ (uint32_t)((brow[j] & 6) << 3));
    }

    // issue one window (4 stages) as a single commit group
    auto issue_window = [&](int w) {
#pragma unroll
        for (int s = 0; s < 4; ++s) {
            int gs = w * 4 + s;
            if (gs < 512) {
                int nt = gs >> 4, ks = gs & 15;
                int b1 = bg * 8 + (nt >> 2), nb1 = nt & 3;
                uint32_t so = (uint32_t)(gs & 7) * B_STG;
                size_t base = ((size_t)(b1 * 1024 + nb1 * 256) * CI + ks * 32) * 2;
#pragma unroll
                for (int j = 0; j < 4; ++j)
                    cp16(bdst[j] + so, gB + base + (size_t)brow[j] * CI * 2 + bco[j]);
            }
        }
        cp_commit();
    };

    // --- ldmatrix fragment addresses ---
    uint32_t aAddr[2], bAddr[4];
#pragma unroll
    for (int mt = 0; mt < 2; ++mt) {
        int mrow = wm * 32 + mt * 16 + (ln & 15);
        uint32_t hi = (uint32_t)(ln >> 4) << 4;
        aAddr[mt] = sb + (uint32_t)(mrow * 64) + (hi ^ (uint32_t)((mrow & 6) << 3));
    }
#pragma unroll
    for (int np = 0; np < 4; ++np) {
        int nrow = wn * 64 + np * 16 + ((ln >> 4) & 1) * 8 + (ln & 7);
        uint32_t hi = (uint32_t)((ln >> 3) & 1) << 4;
        bAddr[np] = bbase + (uint32_t)(nrow * 64) + (hi ^ (uint32_t)((nrow & 6) << 3));
    }

    float acc[2][8][4];
#pragma unroll
    for (int mt = 0; mt < 2; ++mt)
#pragma unroll
        for (int nt = 0; nt < 8; ++nt)
#pragma unroll
            for (int e = 0; e < 4; ++e) acc[mt][nt][e] = 0.f;

    // --- prologue: windows 0 and 1 (each one group) ---
    issue_window(0);
    issue_window(1);

#pragma unroll 1
    for (int w = 0; w < 128; ++w) {
        asm volatile("cp.async.wait_group 1;" ::: "memory");
        __syncthreads();   // window w data visible to all; all warps past w-1

        // --- compute 4 stages, no barriers inside ---
#pragma unroll
        for (int s = 0; s < 4; ++s) {
            const int gs = w * 4 + s;
            const int ks = gs & 15;
            const uint32_t aOff = (uint32_t)(ks * 4096);
            const uint32_t bOff = (uint32_t)(gs & 7) * B_STG;
#pragma unroll
            for (int kt = 0; kt < 2; ++kt) {
                const uint32_t kx = (uint32_t)(kt << 5);
                uint32_t fa[2][4], fb[4][4];
                ldmx4(fa[0], (aAddr[0] + aOff) ^ kx);
                ldmx4(fa[1], (aAddr[1] + aOff) ^ kx);
#pragma unroll
                for (int np = 0; np < 4; ++np)
                    ldmx4(fb[np], (bAddr[np] + bOff) ^ kx);
#pragma unroll
                for (int np = 0; np < 4; ++np)
#pragma unroll
                    for (int mt = 0; mt < 2; ++mt) {
                        mma_f16(acc[mt][2 * np],     fa[mt], fb[np][0], fb[np][1]);
                        mma_f16(acc[mt][2 * np + 1], fa[mt], fb[np][2], fb[np][3]);
                    }
            }

            if (ks == 15) {
                int nt = gs >> 4;
                int b = bg * 8 + (nt >> 2), nblk = nt & 3;
#pragma unroll
                for (int mt = 0; mt < 2; ++mt)
#pragma unroll
                    for (int rr = 0; rr < 2; ++rr) {
                        int o = o0 + wm * 32 + mt * 16 + rr * 8 + g;
                        __half2* zb = (__half2*)(g_z + ((size_t)(b * CO + o) * 9 + tp) * 1024);
#pragma unroll
                        for (int nt8 = 0; nt8 < 8; ++nt8) {
                            int nl = wn * 64 + nt8 * 8 + 2 * t4;
                            int sp = nblk * 256 + nl;
                            zb[sp >> 1] = __floats2half2_rn(acc[mt][nt8][rr * 2],
                                                            acc[mt][nt8][rr * 2 + 1]);
                        }
                    }
#pragma unroll
                for (int mt = 0; mt < 2; ++mt)
#pragma unroll
                    for (int nt8 = 0; nt8 < 8; ++nt8)
#pragma unroll
                        for (int e = 0; e < 4; ++e) acc[mt][nt8][e] = 0.f;
            }
        }

        __syncthreads();   // all warps done reading window w (slots shared w+2)
        issue_window(w + 2);
    }
}

// ---------------------------------------------------------------------------
// Combine v3 (unchanged).
__global__ void __launch_bounds__(256)
k_comb(const float* __restrict__ noise, const float* __restrict__ nwp,
       const float* __restrict__ ab, float* __restrict__ out) {
    extern __shared__ float sm[];
    float* zs = sm;                 // 288*36 = 10368
    float* us = sm + 10368;         // 3*34*64 = 6528
    float* red = sm + 16896;        // 8

    const int bo = blockIdx.x;
    const int b = bo >> 9, o = bo & 511;
    const int tid = threadIdx.x;

    {
        float part = 0.f;
        const float* wrow = g_W2 + (size_t)o * CI;
        const float* srow = g_s + b * CI;
#pragma unroll
        for (int j = tid; j < CI; j += 256) {
            float sv = srow[j];
            part += sv * sv * wrow[j];
        }
#pragma unroll
        for (int off = 16; off; off >>= 1)
            part += __shfl_xor_sync(0xFFFFFFFFu, part, off);
        if ((tid & 31) == 0) red[tid >> 5] = part;
    }

    const __half2* zp2 = (const __half2*)(g_z + (size_t)bo * 9216);
#pragma unroll
    for (int j = tid; j < 4608; j += 256) {
        float2 f = __half22float2(zp2[j]);
        int e = 2 * j;
        int row = e >> 5;
        int q = e & 31;
        *(float2*)(zs + row * 36 + 2 + q) = f;
    }
#pragma unroll
    for (int j = tid; j < 576; j += 256) {
        int row = j >> 1;
        *(float2*)(zs + row * 36 + (j & 1) * 34) = make_float2(0.f, 0.f);
    }
#pragma unroll
    for (int j = tid; j < 192; j += 256) {
        int r = j >> 5;
        int xx = (j & 31) * 2;
        *(float2*)(us + ((r >> 1) * 34 + (r & 1) * 33) * 64 + xx) = make_float2(0.f, 0.f);
    }
    __syncthreads();

    float asum = red[0] + red[1] + red[2] + red[3] +
                 red[4] + red[5] + red[6] + red[7];
    const float alp = 0.014731391274719739f *
                      rsqrtf(asum * (1.0f / 4608.0f) + 1e-8f) * 0.0625f;

#pragma unroll 1
    for (int m = tid; m < 1536; m += 256) {
        int qq = m & 15, y = (m >> 4) & 31, ky = m >> 9;
        const float* r0 = zs + ((ky * 3 + 0) * 32 + y) * 36 + 2 * qq;
        const float* r1 = r0 + 32 * 36;
        const float* r2 = r1 + 32 * 36;
        float2 A0 = *(const float2*)r0, B0 = *(const float2*)(r0 + 2),
               C0 = *(const float2*)(r0 + 4);
        float2 A1 = *(const float2*)r1, B1 = *(const float2*)(r1 + 2),
               C1 = *(const float2*)(r1 + 4);
        float2 A2 = *(const float2*)r2, B2 = *(const float2*)(r2 + 2),
               C2 = *(const float2*)(r2 + 4);
        float p1 = A1.y, p2 = A2.y;
        float q0 = B0.x, q1 = B1.x, q2 = B2.x;
        float s0 = B0.y, s1 = B1.y, s2 = B2.y;
        float t0 = C0.x, t1 = C1.x;
        float4 u;
        u.x = p1 + 3.f * p2 + 3.f * q0 + 3.f * q1 + q2 + s0;
        u.y = p2 + q0 + 3.f * q1 + 3.f * q2 + 3.f * s0 + s1;
        u.z = q1 + 3.f * q2 + 3.f * s0 + 3.f * s1 + s2 + t0;
        u.w = q2 + s0 + 3.f * s1 + 3.f * s2 + 3.f * t0 + t1;
        *(float4*)(us + (ky * 34 + y + 1) * 64 + 4 * qq) = u;
    }
    __syncthreads();

    const float bia = ab[o];
    const float nw = *nwp;
    const float* nzb = noise + b * 4096;
    float* ob = out + (size_t)bo * 4096;
#pragma unroll 1
    for (int m = tid; m < 1024; m += 256) {
        int X2 = (m & 31) * 2, p = m >> 5;
        const float* v0 = us + (0 * 34 + p) * 64 + X2;
        const float* v1 = us + (1 * 34 + p) * 64 + X2;
        const float* v2 = us + (2 * 34 + p) * 64 + X2;
        float2 a01 = *(const float2*)(v0 + 64), a02 = *(const float2*)(v0 + 128);
        float2 a10 = *(const float2*)(v1),      a11 = *(const float2*)(v1 + 64);
        float2 a12 = *(const float2*)(v1 + 128);
        float2 a20 = *(const float2*)(v2),      a21 = *(const float2*)(v2 + 64);
        float2 o0v, o1v;
        o0v.x = a10.x + 3.f * a20.x + 3.f * a01.x + 3.f * a11.x + a21.x + a02.x;
        o0v.y = a10.y + 3.f * a20.y + 3.f * a01.y + 3.f * a11.y + a21.y + a02.y;
        o1v.x = a20.x + a01.x + 3.f * a11.x + 3.f * a21.x + 3.f * a02.x + a12.x;
        o1v.y = a20.y + a01.y + 3.f * a11.y + 3.f * a21.y + 3.f * a02.y + a12.y;
        int j0 = (2 * p) * 64 + X2;
        float2 n0 = *(const float2*)(nzb + j0);
        float2 n1 = *(const float2*)(nzb + j0 + 64);
        float2 w0, w1;
        w0.x = o0v.x * alp + nw * n0.x + bia;
        w0.y = o0v.y * alp + nw * n0.y + bia;
        w1.x = o1v.x * alp + nw * n1.x + bia;
        w1.y = o1v.y * alp + nw * n1.y + bia;
        w0.x = (w0.x > 0.f ? w0.x : 0.2f * w0.x) * 1.4142135623730951f;
        w0.y = (w0.y > 0.f ? w0.y : 0.2f * w0.y) * 1.4142135623730951f;
        w1.x = (w1.x > 0.f ? w1.x : 0.2f * w1.x) * 1.4142135623730951f;
        w1.y = (w1.y > 0.f ? w1.y : 0.2f * w1.y) * 1.4142135623730951f;
        *(float2*)(ob + j0) = w0;
        *(float2*)(ob + j0 + 64) = w1;
    }
}

// ---------------------------------------------------------------------------
extern "C" void kernel_launch(void* const* d_in, const int* in_sizes, int n_in,
                              void* d_out, int out_size) {
    const float* x           = (const float*)d_in[0];
    const float* style       = (const float*)d_in[1];
    const float* noise       = (const float*)d_in[2];
    const float* conv_weight = (const float*)d_in[3];
    const float* mod_weight  = (const float*)d_in[4];
    const float* mod_bias    = (const float*)d_in[5];
    const float* noise_w     = (const float*)d_in[6];
    const float* act_bias    = (const float*)d_in[7];
    float* out = (float*)d_out;

    cudaFuncSetAttribute(k_zgemm, cudaFuncAttributeMaxDynamicSharedMemorySize, SMEM_Z);
    cudaFuncSetAttribute(k_comb, cudaFuncAttributeMaxDynamicSharedMemorySize, 67648);

    // zgemm at launch index 3 -> lands in the ncu capture window.
    k_style<<<NB, 512>>>(style, mod_weight, mod_bias);
    k_prep_w<<<768, 512>>>(conv_weight);
    k_prep_x<<<256, 512>>>(x);
    k_zgemm<<<144, 256, SMEM_Z>>>();
    k_comb<<<NB * CO, 256, 67648>>>(noise, noise_w, act_bias, out);
}

// round 17
// speedup vs baseline: 1.1644x; 1.1037x over previous
#include <cuda_runtime.h>
#include <cuda_fp16.h>
#include <cstdint>
#include <math.h>

#define NB 16
#define CI 512
#define CO 512
#define SD 512

// ---------------------------------------------------------------------------
__device__ float g_s[NB * CI];
__device__ float g_W2[CO * CI];
__device__ __half g_x[(size_t)NB * 32 * 32 * CI];   // [b][y][x][i] fp16, modulated
__device__ __half g_k[(size_t)9 * CO * CI];         // [tap][o][i] fp16
__device__ __half g_z[(size_t)NB * CO * 9 * 1024];  // [b][o][tap][32x32] fp16

// ---------------------------------------------------------------------------
__device__ __forceinline__ unsigned h2u(__half2 h) {
    return *reinterpret_cast<unsigned*>(&h);
}
__device__ __forceinline__ uint32_t smem_u32(const void* p) {
    uint32_t a;
    asm("{ .reg .u64 t; cvta.to.shared.u64 t, %1; cvt.u32.u64 %0, t; }"
        : "=r"(a) : "l"(p));
    return a;
}
__device__ __forceinline__ void cp16(uint32_t dst, const void* src) {
    asm volatile("cp.async.cg.shared.global [%0], [%1], 16;"
                 :: "r"(dst), "l"(src) : "memory");
}
__device__ __forceinline__ void cp_commit() {
    asm volatile("cp.async.commit_group;" ::: "memory");
}
__device__ __forceinline__ void ldmx4(uint32_t* r, uint32_t addr) {
    asm volatile("ldmatrix.sync.aligned.m8n8.x4.shared.b16 {%0,%1,%2,%3}, [%4];"
                 : "=r"(r[0]), "=r"(r[1]), "=r"(r[2]), "=r"(r[3]) : "r"(addr));
}
__device__ __forceinline__ void mma_f16(float* d, const uint32_t* a,
                                        uint32_t b0, uint32_t b1) {
    asm volatile(
        "mma.sync.aligned.m16n8k16.row.col.f32.f16.f16.f32 "
        "{%0,%1,%2,%3}, {%4,%5,%6,%7}, {%8,%9}, {%0,%1,%2,%3};"
        : "+f"(d[0]), "+f"(d[1]), "+f"(d[2]), "+f"(d[3])
        : "r"(a[0]), "r"(a[1]), "r"(a[2]), "r"(a[3]), "r"(b0), "r"(b1));
}

// ---------------------------------------------------------------------------
__global__ void k_style(const float* __restrict__ style, const float* __restrict__ mw,
                        const float* __restrict__ mb) {
    int b = blockIdx.x, i = threadIdx.x;
    __shared__ float st[SD];
    st[i] = style[b * SD + i];
    __syncthreads();
    const float* row = mw + (size_t)i * SD;
    float acc = 0.f;
#pragma unroll 4
    for (int j = 0; j < SD; j += 4) {
        float4 m = *(const float4*)(row + j);
        acc += m.x * st[j] + m.y * st[j + 1] + m.z * st[j + 2] + m.w * st[j + 3];
    }
    g_s[b * CI + i] = acc * 0.04419417382415922f + mb[i];
}

// Fused prep: wsplit (bid<256) | w2 (256..767) | xsplit (768..1023)
__global__ void __launch_bounds__(512)
k_prep(const float* __restrict__ cw, const float* __restrict__ x) {
    int bid = blockIdx.x, tid = threadIdx.x;
    if (bid < 256) {
        int idx = bid * 512 + tid;
        int o = idx >> 8, ipair = idx & 255;
        int i = ipair * 2;
        const float* p0 = cw + ((size_t)o * CI + i) * 9;
        const float* p1 = p0 + 9;
        unsigned* pk = (unsigned*)g_k;
#pragma unroll
        for (int k = 0; k < 9; ++k) {
            unsigned v = h2u(__floats2half2_rn(p0[k], p1[k]));
            pk[((size_t)k * CO + o) * (CI / 2) + ipair] = v;
        }
    } else if (bid < 768) {
        int idx = (bid - 256) * 512 + tid;
        const float* p = cw + (size_t)idx * 9;
        float a = 0.f;
#pragma unroll
        for (int k = 0; k < 9; ++k) a += p[k] * p[k];
        g_W2[idx] = a;
    } else {
        int xb = bid - 768;
        int b = xb >> 4;
        int y = (xb & 15) * 2 + (tid >> 8);
        int ipair = tid & 255;
        int i = ipair * 2;
        const float* s0 = x + ((size_t)(b * CI + i) * 32 + y) * 32;
        const float* s1 = s0 + 1024;
        float sv0 = g_s[b * CI + i], sv1 = g_s[b * CI + i + 1];
        unsigned pk[32];
#pragma unroll
        for (int q4 = 0; q4 < 8; ++q4) {
            float4 f0 = *(const float4*)(s0 + q4 * 4);
            float4 f1 = *(const float4*)(s1 + q4 * 4);
            pk[q4 * 4 + 0] = h2u(__floats2half2_rn(f0.x * sv0, f1.x * sv1));
            pk[q4 * 4 + 1] = h2u(__floats2half2_rn(f0.y * sv0, f1.y * sv1));
            pk[q4 * 4 + 2] = h2u(__floats2half2_rn(f0.z * sv0, f1.z * sv1));
            pk[q4 * 4 + 3] = h2u(__floats2half2_rn(f0.w * sv0, f1.w * sv1));
        }
        unsigned* px = (unsigned*)g_x;
        size_t rowbase = (size_t)(b * 32 + y) * 32 * (CI / 2) + (size_t)ipair;
#pragma unroll
        for (int q = 0; q < 32; ++q)
            px[rowbase + (size_t)q * (CI / 2)] = pk[q];
    }
}

// ---------------------------------------------------------------------------
// Persistent z GEMM (R14 config — measured best 242.9us):
// 288 CTAs (72 row-tiles of M=64 x 4 b-groups). A resident 64KB,
// B 3-stage ring (3x16KB) => 112KB smem/CTA, occupancy 2.
#define A_BYTES 65536
#define B_STG 16384
#define SMEM_Z (A_BYTES + 3 * B_STG)

__global__ void __launch_bounds__(256, 2)
k_zgemm() {
    extern __shared__ __align__(1024) char smem[];
    const uint32_t sb = smem_u32(smem);
    const uint32_t bbase = sb + A_BYTES;

    const int tid = threadIdx.x;
    const int wid = tid >> 5, ln = tid & 31;
    const int rt = blockIdx.x % 72;
    const int bg = blockIdx.x / 72;     // 0..3
    const int tp = rt >> 3;
    const int o0 = (rt & 7) * 64;
    const int wm = wid & 1, wn = wid >> 1;
    const int g = ln >> 2, t4 = ln & 3;

    const char* gA = (const char*)g_k;
    const char* gB = (const char*)g_x;

    // --- load full A (64 x 512 fp16 = 64KB; 16 kchunks of 4KB) ---
    {
        int r = tid >> 2;                        // 0..63
        uint32_t c = (uint32_t)(tid & 3) << 4;
        const char* sA = gA + ((size_t)(tp * CO + o0 + r) * CI) * 2 + c;
        uint32_t dA = sb + (uint32_t)(r * 64) + (c ^ (uint32_t)((r & 6) << 3));
#pragma unroll
        for (int kc = 0; kc < 16; ++kc)
            cp16(dA + kc * 4096, sA + kc * 64);
        cp_commit();
    }

    // --- B stage setup: 4 chunks of 16B per thread per stage (16KB) ---
    int brow[4];
    uint32_t bco[4], bdst[4];
#pragma unroll
    for (int j = 0; j < 4; ++j) {
        int id = tid + 256 * j;
        brow[j] = id >> 2;
        bco[j] = (uint32_t)(id & 3) << 4;
        bdst[j] = bbase + (uint32_t)(brow[j] * 64) +
                  (bco[j] ^ (uint32_t)((brow[j] & 6) << 3));
    }

    // --- ldmatrix fragment addresses ---
    uint32_t aAddr[2], bAddr[4];
#pragma unroll
    for (int mt = 0; mt < 2; ++mt) {
        int mrow = wm * 32 + mt * 16 + (ln & 15);
        uint32_t hi = (uint32_t)(ln >> 4) << 4;
        aAddr[mt] = sb + (uint32_t)(mrow * 64) + (hi ^ (uint32_t)((mrow & 6) << 3));
    }
#pragma unroll
    for (int np = 0; np < 4; ++np) {
        int nrow = wn * 64 + np * 16 + ((ln >> 4) & 1) * 8 + (ln & 7);
        uint32_t hi = (uint32_t)((ln >> 3) & 1) << 4;
        bAddr[np] = bbase + (uint32_t)(nrow * 64) + (hi ^ (uint32_t)((nrow & 6) << 3));
    }

    float acc[2][8][4];
#pragma unroll
    for (int mt = 0; mt < 2; ++mt)
#pragma unroll
        for (int nt = 0; nt < 8; ++nt)
#pragma unroll
            for (int e = 0; e < 4; ++e) acc[mt][nt][e] = 0.f;

    // --- prologue: B stages 0,1 ---
#pragma unroll
    for (int s = 0; s < 2; ++s) {
        int nt1 = s >> 4, ks1 = s & 15;
        int b1 = bg * 4 + (nt1 >> 2), nb1 = nt1 & 3;
        uint32_t so = (uint32_t)(s % 3) * B_STG;
        size_t base = ((size_t)(b1 * 1024 + nb1 * 256) * CI + ks1 * 32) * 2;
#pragma unroll
        for (int j = 0; j < 4; ++j)
            cp16(bdst[j] + so, gB + base + (size_t)brow[j] * CI * 2 + bco[j]);
        cp_commit();
    }

    int slot = 0, slot2 = 2;
#pragma unroll 1
    for (int gs = 0; gs < 256; ++gs) {
        asm volatile("cp.async.wait_group 1;" ::: "memory");
        __syncthreads();

        if (gs + 2 < 256) {
            int g1 = gs + 2;
            int nt1 = g1 >> 4, ks1 = g1 & 15;
            int b1 = bg * 4 + (nt1 >> 2), nb1 = nt1 & 3;
            uint32_t so = (uint32_t)slot2 * B_STG;
            size_t base = ((size_t)(b1 * 1024 + nb1 * 256) * CI + ks1 * 32) * 2;
#pragma unroll
            for (int j = 0; j < 4; ++j)
                cp16(bdst[j] + so, gB + base + (size_t)brow[j] * CI * 2 + bco[j]);
        }
        cp_commit();

        const int ks = gs & 15;
        const uint32_t aOff = (uint32_t)(ks * 4096);
        const uint32_t bOff = (uint32_t)slot * B_STG;
#pragma unroll
        for (int kt = 0; kt < 2; ++kt) {
            const uint32_t kx = (uint32_t)(kt << 5);
            uint32_t fa[2][4], fb[4][4];
            ldmx4(fa[0], (aAddr[0] + aOff) ^ kx);
            ldmx4(fa[1], (aAddr[1] + aOff) ^ kx);
#pragma unroll
            for (int np = 0; np < 4; ++np)
                ldmx4(fb[np], (bAddr[np] + bOff) ^ kx);
#pragma unroll
            for (int np = 0; np < 4; ++np)
#pragma unroll
                for (int mt = 0; mt < 2; ++mt) {
                    mma_f16(acc[mt][2 * np],     fa[mt], fb[np][0], fb[np][1]);
                    mma_f16(acc[mt][2 * np + 1], fa[mt], fb[np][2], fb[np][3]);
                }
        }

        slot = (slot == 2) ? 0 : slot + 1;
        slot2 = (slot2 == 2) ? 0 : slot2 + 1;

        if (ks == 15) {
            int nt = gs >> 4;
            int b = bg * 4 + (nt >> 2), nblk = nt & 3;
#pragma unroll
            for (int mt = 0; mt < 2; ++mt)
#pragma unroll
                for (int rr = 0; rr < 2; ++rr) {
                    int o = o0 + wm * 32 + mt * 16 + rr * 8 + g;
                    __half2* zb = (__half2*)(g_z + ((size_t)(b * CO + o) * 9 + tp) * 1024);
#pragma unroll
                    for (int nt8 = 0; nt8 < 8; ++nt8) {
                        int nl = wn * 64 + nt8 * 8 + 2 * t4;
                        int sp = nblk * 256 + nl;
                        zb[sp >> 1] = __floats2half2_rn(acc[mt][nt8][rr * 2],
                                                        acc[mt][nt8][rr * 2 + 1]);
                    }
                }
#pragma unroll
            for (int mt = 0; mt < 2; ++mt)
#pragma unroll
                for (int nt8 = 0; nt8 < 8; ++nt8)
#pragma unroll
                    for (int e = 0; e < 4; ++e) acc[mt][nt8][e] = 0.f;
        }
    }
}

// ---------------------------------------------------------------------------
// Combine v4: 512 threads (3 CTAs/SM => 1536 thr/SM, ~2x occupancy of v3).
__global__ void __launch_bounds__(512)
k_comb(const float* __restrict__ noise, const float* __restrict__ nwp,
       const float* __restrict__ ab, float* __restrict__ out) {
    extern __shared__ float sm[];
    float* zs = sm;                 // 288*36 = 10368
    float* us = sm + 10368;         // 3*34*64 = 6528
    float* red = sm + 16896;        // 16

    const int bo = blockIdx.x;
    const int b = bo >> 9, o = bo & 511;
    const int tid = threadIdx.x;

    // fused alpha partial
    {
        float part = 0.f;
        const float* wrow = g_W2 + (size_t)o * CI;
        const float* srow = g_s + b * CI;
        {
            int j = tid;
            if (j < CI) {
                float sv = srow[j];
                part += sv * sv * wrow[j];
            }
        }
#pragma unroll
        for (int off = 16; off; off >>= 1)
            part += __shfl_xor_sync(0xFFFFFFFFu, part, off);
        if ((tid & 31) == 0) red[tid >> 5] = part;
    }

    // stage z -> padded fp32 zs (float2 stores, aligned)
    const __half2* zp2 = (const __half2*)(g_z + (size_t)bo * 9216);
#pragma unroll
    for (int j = tid; j < 4608; j += 512) {
        float2 f = __half22float2(zp2[j]);
        int e = 2 * j;
        int row = e >> 5;
        int q = e & 31;
        *(float2*)(zs + row * 36 + 2 + q) = f;
    }
#pragma unroll
    for (int j = tid; j < 576; j += 512) {
        int row = j >> 1;
        *(float2*)(zs + row * 36 + (j & 1) * 34) = make_float2(0.f, 0.f);
    }
    if (tid < 192) {
        int r = tid >> 5;
        int xx = (tid & 31) * 2;
        *(float2*)(us + ((r >> 1) * 34 + (r & 1) * 33) * 64 + xx) = make_float2(0.f, 0.f);
    }
    __syncthreads();

    float asum = 0.f;
#pragma unroll
    for (int w = 0; w < 16; ++w) asum += red[w];
    const float alp = 0.014731391274719739f *
                      rsqrtf(asum * (1.0f / 4608.0f) + 1e-8f) * 0.0625f;

    // x-pass: 1536 items, each -> u[4qq..4qq+3] (float4 store)
#pragma unroll
    for (int m = tid; m < 1536; m += 512) {
        int qq = m & 15, y = (m >> 4) & 31, ky = m >> 9;
        const float* r0 = zs + ((ky * 3 + 0) * 32 + y) * 36 + 2 * qq;
        const float* r1 = r0 + 32 * 36;
        const float* r2 = r1 + 32 * 36;
        float2 A0 = *(const float2*)r0, B0 = *(const float2*)(r0 + 2),
               C0 = *(const float2*)(r0 + 4);
        float2 A1 = *(const float2*)r1, B1 = *(const float2*)(r1 + 2),
               C1 = *(const float2*)(r1 + 4);
        float2 A2 = *(const float2*)r2, B2 = *(const float2*)(r2 + 2),
               C2 = *(const float2*)(r2 + 4);
        float p1 = A1.y, p2 = A2.y;
        float q0 = B0.x, q1 = B1.x, q2 = B2.x;
        float s0 = B0.y, s1 = B1.y, s2 = B2.y;
        float t0 = C0.x, t1 = C1.x;
        float4 u;
        u.x = p1 + 3.f * p2 + 3.f * q0 + 3.f * q1 + q2 + s0;
        u.y = p2 + q0 + 3.f * q1 + 3.f * q2 + 3.f * s0 + s1;
        u.z = q1 + 3.f * q2 + 3.f * s0 + 3.f * s1 + s2 + t0;
        u.w = q2 + s0 + 3.f * s1 + 3.f * s2 + 3.f * t0 + t1;
        *(float4*)(us + (ky * 34 + y + 1) * 64 + 4 * qq) = u;
    }
    __syncthreads();

    // y-pass: 1024 items
    const float bia = ab[o];
    const float nw = *nwp;
    const float* nzb = noise + b * 4096;
    float* ob = out + (size_t)bo * 4096;
#pragma unroll
    for (int m = tid; m < 1024; m += 512) {
        int X2 = (m & 31) * 2, p = m >> 5;
        const float* v0 = us + (0 * 34 + p) * 64 + X2;
        const float* v1 = us + (1 * 34 + p) * 64 + X2;
        const float* v2 = us + (2 * 34 + p) * 64 + X2;
        float2 a01 = *(const float2*)(v0 + 64), a02 = *(const float2*)(v0 + 128);
        float2 a10 = *(const float2*)(v1),      a11 = *(const float2*)(v1 + 64);
        float2 a12 = *(const float2*)(v1 + 128);
        float2 a20 = *(const float2*)(v2),      a21 = *(const float2*)(v2 + 64);
        float2 o0v, o1v;
        o0v.x = a10.x + 3.f * a20.x + 3.f * a01.x + 3.f * a11.x + a21.x + a02.x;
        o0v.y = a10.y + 3.f * a20.y + 3.f * a01.y + 3.f * a11.y + a21.y + a02.y;
        o1v.x = a20.x + a01.x + 3.f * a11.x + 3.f * a21.x + 3.f * a02.x + a12.x;
        o1v.y = a20.y + a01.y + 3.f * a11.y + 3.f * a21.y + 3.f * a02.y + a12.y;
        int j0 = (2 * p) * 64 + X2;
        float2 n0 = *(const float2*)(nzb + j0);
        float2 n1 = *(const float2*)(nzb + j0 + 64);
        float2 w0, w1;
        w0.x = o0v.x * alp + nw * n0.x + bia;
        w0.y = o0v.y * alp + nw * n0.y + bia;
        w1.x = o1v.x * alp + nw * n1.x + bia;
        w1.y = o1v.y * alp + nw * n1.y + bia;
        w0.x = (w0.x > 0.f ? w0.x : 0.2f * w0.x) * 1.4142135623730951f;
        w0.y = (w0.y > 0.f ? w0.y : 0.2f * w0.y) * 1.4142135623730951f;
        w1.x = (w1.x > 0.f ? w1.x : 0.2f * w1.x) * 1.4142135623730951f;
        w1.y = (w1.y > 0.f ? w1.y : 0.2f * w1.y) * 1.4142135623730951f;
        *(float2*)(ob + j0) = w0;
        *(float2*)(ob + j0 + 64) = w1;
    }
}

// ---------------------------------------------------------------------------
extern "C" void kernel_launch(void* const* d_in, const int* in_sizes, int n_in,
                              void* d_out, int out_size) {
    const float* x           = (const float*)d_in[0];
    const float* style       = (const float*)d_in[1];
    const float* noise       = (const float*)d_in[2];
    const float* conv_weight = (const float*)d_in[3];
    const float* mod_weight  = (const float*)d_in[4];
    const float* mod_bias    = (const float*)d_in[5];
    const float* noise_w     = (const float*)d_in[6];
    const float* act_bias    = (const float*)d_in[7];
    float* out = (float*)d_out;

    cudaFuncSetAttribute(k_zgemm, cudaFuncAttributeMaxDynamicSharedMemorySize, SMEM_Z);
    cudaFuncSetAttribute(k_comb, cudaFuncAttributeMaxDynamicSharedMemorySize, 67648);

    // comb at launch index 3 -> lands in the ncu capture window.
    k_style<<<NB, 512>>>(style, mod_weight, mod_bias);
    k_prep<<<1024, 512>>>(conv_weight, x);
    k_zgemm<<<288, 256, SMEM_Z>>>();
    k_comb<<<NB * CO, 512, 67648>>>(noise, noise_w, act_bias, out);
}